// round 14
// baseline (speedup 1.0000x reference)
#include <cuda_runtime.h>

// ---------------------------------------------------------------------------
// 2-D elastic staggered-grid FDTD, persistent kernel, k=2 time blocking,
// tagged-chunk single-RTT z-exchange (R8 protocol), TWO INDEPENDENT BATCHES
// PER CTA: 64 CTAs x 384 threads. Group g (threads g*192..g*192+191) runs
// batch 2*(cta/32)+g on z-tile cta%32. The groups share NO data - each has
// its own SMEM mirror set and its own message chain (chain id b*32+tz) -
// they only share the four per-iteration __syncthreads (uniform control
// flow, identical work -> negligible skew, provably deadlock-free). With
// 12 warps/CTA (3 per SMSP) the LDS/poll latency of one group is hidden
// behind the other group's issue stream.
//
// Per-group structure is EXACTLY R8/R13: one thread per column, 6 rows of
// all 5 fields in registers, SMEM x-neighbor mirrors, ghost-zone redundant
// computation, 16-byte tagged chunks (payload+tag in one ld/st.global.cg.v4,
// slot = iteration parity, tag==i-1 equality poll; producer overwrite of
// slot i&1 cannot race a lagging reader because entry into iter i
// data-depends on the neighbor having consumed slot i-2).
//
// Output layout (reference): (NT, NREC, 2*B):
//   out[t*NREC*8 + r*8 + comp*4 + b], comp 0 = vx, comp 1 = vz.
// ---------------------------------------------------------------------------

namespace {
constexpr int B_    = 4;
constexpr int NT_   = 256;
constexpr int NZ_   = 192;
constexpr int NX_   = 192;
constexpr int NREC_ = 128;
constexpr int RZ_   = 6;                 // rows per tile
constexpr int NTILES_ = NZ_ / RZ_;       // 32
constexpr int NCHAIN_ = B_ * NTILES_;    // 128 logical chains (b, tz)
constexpr int NCTA_   = NCHAIN_ / 2;     // 64 CTAs, 2 chains each
constexpr int NTHR_   = 2 * NX_;         // 384 threads
constexpr int NIT_    = NT_ / 2;         // 128 iterations
constexpr float DT_ = 0.001f;
constexpr float DH_ = 10.0f;
}

struct __align__(16) Chunk { float a, b, c; int tag; };

// double-buffered tagged message chunks: [slot][chain][chunk 0..2][x]
__device__ Chunk g_dnC[2][NCHAIN_][3][NX_];
__device__ Chunk g_upC[2][NCHAIN_][3][NX_];

__device__ __forceinline__ void ldcg_v4(const Chunk* p, float& a, float& b,
                                        float& c, int& t) {
    asm volatile("ld.global.cg.v4.b32 {%0,%1,%2,%3}, [%4];"
                 : "=f"(a), "=f"(b), "=f"(c), "=r"(t) : "l"(p));
}
__device__ __forceinline__ void stcg_v4(Chunk* p, float a, float b, float c, int t) {
    asm volatile("st.global.cg.v4.b32 [%0], {%1,%2,%3,%4};"
                 :: "l"(p), "f"(a), "f"(b), "f"(c), "r"(t) : "memory");
}

__global__ void init_msgs_kernel() {
    int i = blockIdx.x * blockDim.x + threadIdx.x;
    int n = 2 * NCHAIN_ * 3 * NX_ * 4;          // total 32-bit words per array
    if (i < n) {
        ((int*)g_dnC)[i] = 0;
        ((int*)g_upC)[i] = 0;
    }
}

__global__ void __launch_bounds__(NTHR_, 1) wave_kernel(
    const float* __restrict__ xsrc,    // (B, NT)
    const float* __restrict__ vp,      // (NZ, NX)
    const float* __restrict__ vs,
    const float* __restrict__ rho,
    const int*   __restrict__ src_loc, // (B, 2)
    const int*   __restrict__ rec_loc, // (NREC, 2)
    float*       __restrict__ out)     // (NT, NREC, 2*B)
{
    const int cta = blockIdx.x;
    const int tz  = cta % NTILES_;               // z-tile (shared by both groups)
    const int bp  = cta / NTILES_;               // batch pair 0..1
    const int grp = threadIdx.x / NX_;           // group 0/1
    const int x   = threadIdx.x % NX_;
    const int b   = 2 * bp + grp;                // my batch
    const int cid = b * NTILES_ + tz;            // my message chain id
    const bool has_top = (tz > 0);
    const bool has_bot = (tz < NTILES_ - 1);
    const int xm = (x == 0) ? 0 : x - 1;              // clamp -> zero diff at edge
    const int xp = (x == NX_ - 1) ? NX_ - 1 : x + 1;

    // per-group SMEM mirror sets (no sharing between groups)
    __shared__ float s_vx_a [2][RZ_][NX_];
    __shared__ float s_vz_a [2][RZ_][NX_];
    __shared__ float s_txx_a[2][RZ_][NX_];
    __shared__ float s_txz_a[2][RZ_][NX_];
    __shared__ float sh_vxa1_a[2][NX_], sh_vza1_a[2][NX_], sh_txza1_a[2][NX_];
    __shared__ float sh_vxp1_a[2][NX_], sh_vzp1_a[2][NX_], sh_txxp1_a[2][NX_];
    float (*s_vx)[NX_]  = s_vx_a[grp];
    float (*s_vz)[NX_]  = s_vz_a[grp];
    float (*s_txx)[NX_] = s_txx_a[grp];
    float (*s_txz)[NX_] = s_txz_a[grp];
    float* sh_vxa1 = sh_vxa1_a[grp];
    float* sh_vza1 = sh_vza1_a[grp];
    float* sh_txza1 = sh_txza1_a[grp];
    float* sh_vxp1 = sh_vxp1_a[grp];
    float* sh_vzp1 = sh_vzp1_a[grp];
    float* sh_txxp1 = sh_txxp1_a[grp];

    // per-cell material coefficients (DT, 1/DH folded in)
    float bc[RZ_], cl2m[RZ_], clam[RZ_], cmu[RZ_];
    #pragma unroll
    for (int r = 0; r < RZ_; ++r) {
        int gi = (tz * RZ_ + r) * NX_ + x;
        float vpv = __ldg(&vp[gi]);
        float vsv = __ldg(&vs[gi]);
        float rh  = __ldg(&rho[gi]);
        float mu  = rh * vsv * vsv;
        float lam = rh * (vpv * vpv - 2.0f * vsv * vsv);
        bc[r]   = DT_ / (rh * DH_);
        cl2m[r] = (DT_ / DH_) * (lam + 2.0f * mu);
        clam[r] = (DT_ / DH_) * lam;
        cmu[r]  = (DT_ / DH_) * mu;
    }
    // ghost-row coefficients: a=z0-1, b=z0-2 (top), p=z1+1, q=z1+2 (bottom)
    float bA=0, bB=0, clamA=0, cl2mA=0, cmuA=0;
    float bP=0, bQ=0, clamP=0, cl2mP=0, cmuP=0;
    if (has_top) {
        int ga = (tz * RZ_ - 1) * NX_ + x;
        int gb = (tz * RZ_ - 2) * NX_ + x;
        float vpv = __ldg(&vp[ga]), vsv = __ldg(&vs[ga]), rh = __ldg(&rho[ga]);
        float mu  = rh * vsv * vsv;
        float lam = rh * (vpv * vpv - 2.0f * vsv * vsv);
        bA = DT_ / (rh * DH_);
        cl2mA = (DT_ / DH_) * (lam + 2.0f * mu);
        clamA = (DT_ / DH_) * lam;
        cmuA  = (DT_ / DH_) * mu;
        bB = DT_ / (__ldg(&rho[gb]) * DH_);
    }
    if (has_bot) {
        int gp = (tz * RZ_ + RZ_) * NX_ + x;
        int gq = (tz * RZ_ + RZ_ + 1) * NX_ + x;
        float vpv = __ldg(&vp[gp]), vsv = __ldg(&vs[gp]), rh = __ldg(&rho[gp]);
        float mu  = rh * vsv * vsv;
        float lam = rh * (vpv * vpv - 2.0f * vsv * vsv);
        bP = DT_ / (rh * DH_);
        cl2mP = (DT_ / DH_) * (lam + 2.0f * mu);
        clamP = (DT_ / DH_) * lam;
        cmuP  = (DT_ / DH_) * mu;
        bQ = DT_ / (__ldg(&rho[gq]) * DH_);
    }

    // wavefields, zero initial conditions
    float vx[RZ_]  = {}, vz[RZ_]  = {};
    float txx[RZ_] = {}, tzz[RZ_] = {}, txz[RZ_] = {};
    #pragma unroll
    for (int r = 0; r < RZ_; ++r) {
        s_vx[r][x] = 0.f; s_vz[r][x] = 0.f; s_txx[r][x] = 0.f; s_txz[r][x] = 0.f;
    }

    // source ownership (per my batch)
    const int ssz = src_loc[2 * b];
    const int ssx = src_loc[2 * b + 1];
    const bool is_src = ((ssz / RZ_) == tz) && (x == ssx);
    const int src_lr  = ssz % RZ_;
    const bool src_at_a = has_top && (ssz == tz * RZ_ - 1)  && (x == ssx);
    const bool src_at_p = has_bot && (ssz == tz * RZ_ + RZ_) && (x == ssx);

    // receiver ownership: thread x doubles as receiver index within my group
    bool is_rec = false;
    int my_lrz = 0, my_rx = 0;
    if (x < NREC_) {
        int rz = rec_loc[2 * x];
        my_rx  = rec_loc[2 * x + 1];
        if ((rz / RZ_) == tz) { is_rec = true; my_lrz = rz % RZ_; }
    }

    const float2* xsrc2 = reinterpret_cast<const float2*>(xsrc + b * NT_);

    __syncthreads();

    for (int i = 1; i <= NIT_; ++i) {
        const int t1 = 2 * i - 1;
        const int t2 = 2 * i;
        const float2 wv = __ldg(&xsrc2[i - 1]);   // {xsrc[t1-1], xsrc[t2-1]}
        const float w1 = wv.x;
        const float w2 = wv.y;

        // ---- V1 interior rows 1..RZ-2 (no message dependence) ----
        #pragma unroll
        for (int r = 1; r < RZ_ - 1; ++r) {
            float txx_c = txx[r], txz_c = txz[r];
            vx[r] += bc[r] * ((s_txx[r][xp] - txx_c) + (txz_c - txz[r - 1]));
            vz[r] += bc[r] * ((txz_c - s_txz[r][xm]) + (tzz[r + 1] - tzz[r]));
        }

        // ---- per-lane tagged message poll (ONE RTT, no barrier) ----
        const int want = i - 1;
        const int pr = want & 1;
        float t_vx=0, t_txx_x=0, t_txz_x=0, t_txx_xp=0, t_txz_xm=0;
        float t_vz=0, t_tzz=0, t_txz2=0, t_txz2_xm=0, t_vz2=0, t_tzz2=0;
        float b_vx=0, b_txx_x=0, b_txz_x=0, b_txx_xp=0, b_txz_xm=0;
        float b_vz=0, b_tzz=0, b_vx2=0, b_txx2=0, b_txz2=0, b_tzz2=0, b_txx2_xp=0;
        {
            const Chunk* dn = has_top ? &g_dnC[pr][cid - 1][0][0] : nullptr;
            const Chunk* up = has_bot ? &g_upC[pr][cid + 1][0][0] : nullptr;
            bool top_ok = !has_top, bot_ok = !has_bot;
            do {
                if (!top_ok) {
                    int g0,g1,g2,g3,g4,g5; float u;
                    ldcg_v4(dn + 0*NX_ + x,  t_vx,   t_txx_x, t_txz_x,  g0);
                    ldcg_v4(dn + 0*NX_ + xm, u,      u,       t_txz_xm, g1);
                    ldcg_v4(dn + 0*NX_ + xp, u,      t_txx_xp,u,        g2);
                    ldcg_v4(dn + 1*NX_ + x,  t_vz,   t_tzz,   t_txz2,   g3);
                    ldcg_v4(dn + 1*NX_ + xm, u,      u,       t_txz2_xm,g4);
                    ldcg_v4(dn + 2*NX_ + x,  t_vz2,  t_tzz2,  u,        g5);
                    top_ok = (g0==want)&(g1==want)&(g2==want)&(g3==want)&(g4==want)&(g5==want);
                }
                if (!bot_ok) {
                    int g0,g1,g2,g3,g4,g5; float u;
                    ldcg_v4(up + 0*NX_ + x,  b_vx,   b_txx_x, b_txz_x,  g0);
                    ldcg_v4(up + 0*NX_ + xm, u,      u,       b_txz_xm, g1);
                    ldcg_v4(up + 0*NX_ + xp, u,      b_txx_xp,u,        g2);
                    ldcg_v4(up + 1*NX_ + x,  b_vz,   b_tzz,   b_vx2,    g3);
                    ldcg_v4(up + 2*NX_ + x,  b_txx2, b_txz2,  b_tzz2,   g4);
                    ldcg_v4(up + 2*NX_ + xp, b_txx2_xp, u,    u,        g5);
                    bot_ok = (g0==want)&(g1==want)&(g2==want)&(g3==want)&(g4==want)&(g5==want);
                }
            } while (!(top_ok && bot_ok));
        }
        // overlap: independent interior SMEM stores
        #pragma unroll
        for (int r = 1; r < RZ_ - 1; ++r) { s_vx[r][x] = vx[r]; s_vz[r][x] = vz[r]; }

        // ---- ghost t+1 velocities ----
        float vza1=0, vzb1=0, vxa1=0, vxp1=0, vxq1=0, vzp1=0;
        if (has_top) {
            vza1 = t_vz  + bA * ((t_txz_x  - t_txz_xm)  + (tzz[0] - t_tzz));
            vzb1 = t_vz2 + bB * ((t_txz2   - t_txz2_xm) + (t_tzz  - t_tzz2));
            vxa1 = t_vx  + bA * ((t_txx_xp - t_txx_x)   + (t_txz_x - t_txz2));
        }
        if (has_bot) {
            vxp1 = b_vx  + bP * ((b_txx_xp  - b_txx_x) + (b_txz_x - txz[RZ_ - 1]));
            vxq1 = b_vx2 + bQ * ((b_txx2_xp - b_txx2)  + (b_txz2  - b_txz_x));
            vzp1 = b_vz  + bP * ((b_txz_x   - b_txz_xm) + (b_tzz2 - b_tzz));
        }

        // ---- V1 edge rows 0 and RZ-1 ----
        {
            float txz_zm = has_top ? t_txz_x : txz[0];
            vx[0] += bc[0] * ((s_txx[0][xp] - txx[0]) + (txz[0] - txz_zm));
            vz[0] += bc[0] * ((txz[0] - s_txz[0][xm]) + (tzz[1] - tzz[0]));
            constexpr int r = RZ_ - 1;
            float tzz_zp = has_bot ? b_tzz : tzz[r];
            vx[r] += bc[r] * ((s_txx[r][xp] - txx[r]) + (txz[r] - txz[r - 1]));
            vz[r] += bc[r] * ((txz[r] - s_txz[r][xm]) + (tzz_zp - tzz[r]));
        }
        s_vx[0][x] = vx[0];             s_vz[0][x] = vz[0];
        s_vx[RZ_ - 1][x] = vx[RZ_ - 1]; s_vz[RZ_ - 1][x] = vz[RZ_ - 1];
        sh_vxa1[x] = vxa1; sh_vza1[x] = vza1;
        sh_vxp1[x] = vxp1; sh_vzp1[x] = vzp1;
        __syncthreads();   // (2)

        // record t1
        if (is_rec) {
            int base = (t1 - 1) * (NREC_ * 2 * B_) + x * (2 * B_);
            out[base + b]      = s_vx[my_lrz][my_rx];
            out[base + B_ + b] = s_vz[my_lrz][my_rx];
        }

        // ---- ghost t+1 edge stresses ----
        float tzza1=0, txza1=0, txxp1=0, tzzp1=0, txzp1=0;
        if (has_top) {
            tzza1 = t_tzz + clamA * (vxa1 - sh_vxa1[xm]) + cl2mA * (vza1 - vzb1);
            if (src_at_a) tzza1 += w1;
            txza1 = t_txz_x + cmuA * ((vx[0] - vxa1) + (sh_vza1[xp] - vza1));
        }
        if (has_bot) {
            float dvx_p = vxp1 - sh_vxp1[xm];
            float dvz_p = vzp1 - vz[RZ_ - 1];
            txxp1 = b_txx_x + cl2mP * dvx_p + clamP * dvz_p;
            tzzp1 = b_tzz   + clamP * dvx_p + cl2mP * dvz_p;
            if (src_at_p) { txxp1 += w1; tzzp1 += w1; }
            txzp1 = b_txz_x + cmuP * ((vxq1 - vxp1) + (sh_vzp1[xp] - vzp1));
        }

        // ------------------ S1 ------------------
        #pragma unroll
        for (int r = 0; r < RZ_; ++r) {
            float vx_c = vx[r], vz_c = vz[r];
            float vz_zm = (r > 0) ? vz[r - 1] : (has_top ? vza1 : vz_c);
            float vx_zp = (r < RZ_ - 1) ? vx[r + 1] : (has_bot ? vxp1 : vx_c);
            float dvx = vx_c - s_vx[r][xm];
            float dvz = vz_c - vz_zm;
            txx[r] += cl2m[r] * dvx + clam[r] * dvz;
            tzz[r] += clam[r] * dvx + cl2m[r] * dvz;
            txz[r] += cmu[r] * ((vx_zp - vx_c) + (s_vz[r][xp] - vz_c));
        }
        if (is_src) {
            #pragma unroll
            for (int r = 0; r < RZ_; ++r)
                if (r == src_lr) { txx[r] += w1; tzz[r] += w1; }
        }
        #pragma unroll
        for (int r = 0; r < RZ_; ++r) { s_txx[r][x] = txx[r]; s_txz[r][x] = txz[r]; }
        sh_txza1[x] = txza1; sh_txxp1[x] = txxp1;
        __syncthreads();   // (3)

        // ---- ghost t+2 edge velocities ----
        float vza2 = 0, vxp2 = 0;
        if (has_top)
            vza2 = vza1 + bA * ((txza1 - sh_txza1[xm]) + (tzz[0] - tzza1));
        if (has_bot)
            vxp2 = vxp1 + bP * ((sh_txxp1[xp] - txxp1) + (txzp1 - txz[RZ_ - 1]));

        // ------------------ V2 ------------------
        #pragma unroll
        for (int r = 0; r < RZ_; ++r) {
            float txx_c = txx[r], txz_c = txz[r];
            float txz_zm = (r > 0) ? txz[r - 1] : (has_top ? txza1 : txz_c);
            float tzz_zp = (r < RZ_ - 1) ? tzz[r + 1] : (has_bot ? tzzp1 : tzz[r]);
            vx[r] += bc[r] * ((s_txx[r][xp] - txx_c) + (txz_c - txz_zm));
            vz[r] += bc[r] * ((txz_c - s_txz[r][xm]) + (tzz_zp - tzz[r]));
        }
        #pragma unroll
        for (int r = 0; r < RZ_; ++r) { s_vx[r][x] = vx[r]; s_vz[r][x] = vz[r]; }
        __syncthreads();   // (4)

        // ---- S2 apron rows {0,1,RZ-2,RZ-1} first, then per-lane publish ----
        #pragma unroll
        for (int rr = 0; rr < 4; ++rr) {
            const int r = (rr < 2) ? rr : RZ_ - 4 + rr;   // 0,1,RZ-2,RZ-1
            float vx_c = vx[r], vz_c = vz[r];
            float vz_zm = (r > 0) ? vz[r - 1] : (has_top ? vza2 : vz_c);
            float vx_zp = (r < RZ_ - 1) ? vx[r + 1] : (has_bot ? vxp2 : vx_c);
            float dvx = vx_c - s_vx[r][xm];
            float dvz = vz_c - vz_zm;
            txx[r] += cl2m[r] * dvx + clam[r] * dvz;
            tzz[r] += clam[r] * dvx + cl2m[r] * dvz;
            txz[r] += cmu[r] * ((vx_zp - vx_c) + (s_vz[r][xp] - vz_c));
            if (is_src && r == src_lr) { txx[r] += w2; tzz[r] += w2; }
        }
        // publish t+2 apron, tag = i (per-lane, no barrier, no flag)
        {
            const int pw = i & 1;
            Chunk* dnp = &g_dnC[pw][cid][0][0];
            stcg_v4(dnp + 0*NX_ + x, vx[RZ_-1], txx[RZ_-1], txz[RZ_-1], i);
            stcg_v4(dnp + 1*NX_ + x, vz[RZ_-1], tzz[RZ_-1], txz[RZ_-2], i);
            stcg_v4(dnp + 2*NX_ + x, vz[RZ_-2], tzz[RZ_-2], 0.f,        i);
            Chunk* upp = &g_upC[pw][cid][0][0];
            stcg_v4(upp + 0*NX_ + x, vx[0], txx[0], txz[0], i);
            stcg_v4(upp + 1*NX_ + x, vz[0], tzz[0], vx[1],  i);
            stcg_v4(upp + 2*NX_ + x, txx[1], txz[1], tzz[1], i);
        }

        // record t2 (s_vx/s_vz valid since sync 4; S2 doesn't touch them)
        if (is_rec) {
            int base = (t2 - 1) * (NREC_ * 2 * B_) + x * (2 * B_);
            out[base + b]      = s_vx[my_lrz][my_rx];
            out[base + B_ + b] = s_vz[my_lrz][my_rx];
        }

        // ---- S2 interior rows 2..RZ-3 (off the inter-CTA critical path) ----
        #pragma unroll
        for (int r = 2; r < RZ_ - 2; ++r) {
            float vx_c = vx[r], vz_c = vz[r];
            float dvx = vx_c - s_vx[r][xm];
            float dvz = vz_c - vz[r - 1];
            txx[r] += cl2m[r] * dvx + clam[r] * dvz;
            tzz[r] += clam[r] * dvx + cl2m[r] * dvz;
            txz[r] += cmu[r] * ((vx[r + 1] - vx_c) + (s_vz[r][xp] - vz_c));
            if (is_src && r == src_lr) { txx[r] += w2; tzz[r] += w2; }
        }
        #pragma unroll
        for (int r = 0; r < RZ_; ++r) { s_txx[r][x] = txx[r]; s_txz[r][x] = txz[r]; }
        __syncthreads();   // (6) — next iter's V1 reads s_txx/s_txz
    }
}

extern "C" void kernel_launch(void* const* d_in, const int* in_sizes, int n_in,
                              void* d_out, int out_size) {
    const float* x   = (const float*)d_in[0];
    const float* vp  = (const float*)d_in[1];
    const float* vs  = (const float*)d_in[2];
    const float* rho = (const float*)d_in[3];
    const int* src   = (const int*)d_in[4];
    const int* rec   = (const int*)d_in[5];
    float* out = (float*)d_out;

    // re-zero message slots (tags -> 0) so every graph replay is identical
    int n = 2 * NCHAIN_ * 3 * NX_ * 4;
    init_msgs_kernel<<<(n + 255) / 256, 256>>>();
    wave_kernel<<<NCTA_, NTHR_>>>(x, vp, vs, rho, src, rec, out);
}

// round 15
// speedup vs baseline: 1.3894x; 1.3894x over previous
#include <cuda_runtime.h>

// ---------------------------------------------------------------------------
// 2-D elastic staggered-grid FDTD, persistent kernel, k=2 time blocking.
// R8/R13 structure (the proven optimum of this session): one thread per
// column, 6 rows of all 5 fields in registers, SMEM x-neighbor mirrors,
// 4 barriers per 2-step iteration, tagged-chunk single-RTT z-exchange.
//
// R13 -> R15 (only change): the FIRST-ATTEMPT message loads are issued at
// the very top of the iteration, before V1-interior compute, so their L2
// latency is hidden under ~150 cycles of independent work. Values are only
// consumed after the tag check passes (speculation safe by construction);
// the retry loop is unchanged.
//
// Chunk layout per column x (slot = iter parity):
//   dn (c -> c+1, c's LAST rows):  A={vx5,txx5,txz5,tag} B={vz5,tzz5,txz4,tag}
//                                  C={vz4,tzz4,0,tag}
//   up (c -> c-1, c's FIRST rows): D={vx0,txx0,txz0,tag} E={vz0,tzz0,vx1,tag}
//                                  F={txx1,txz1,tzz1,tag}
//
// Race-safety: tag==i-1 equality poll; producer overwrite of slot i&1 cannot
// race a lagging reader because the producer's entry into iter i data-depends
// (through the neighbor's published values) on the neighbor having consumed
// the i-2 contents of that slot. 16B v4 accesses are single L2 transactions
// on sm_103a, so tag and payload are atomic per chunk.
//
// Output layout (reference): (NT, NREC, 2*B):
//   out[t*NREC*8 + r*8 + comp*4 + b], comp 0 = vx, comp 1 = vz.
// ---------------------------------------------------------------------------

namespace {
constexpr int B_    = 4;
constexpr int NT_   = 256;
constexpr int NZ_   = 192;
constexpr int NX_   = 192;
constexpr int NREC_ = 128;
constexpr int RZ_   = 6;                 // rows per tile
constexpr int NTILES_ = NZ_ / RZ_;       // 32
constexpr int NCTA_   = B_ * NTILES_;    // 128 (< 148 SMs -> all co-resident)
constexpr int NIT_    = NT_ / 2;         // 128 iterations
constexpr float DT_ = 0.001f;
constexpr float DH_ = 10.0f;
}

struct __align__(16) Chunk { float a, b, c; int tag; };

// double-buffered tagged message chunks: [slot][cta][chunk 0..2][x]
__device__ Chunk g_dnC[2][NCTA_][3][NX_];
__device__ Chunk g_upC[2][NCTA_][3][NX_];

__device__ __forceinline__ void ldcg_v4(const Chunk* p, float& a, float& b,
                                        float& c, int& t) {
    asm volatile("ld.global.cg.v4.b32 {%0,%1,%2,%3}, [%4];"
                 : "=f"(a), "=f"(b), "=f"(c), "=r"(t) : "l"(p));
}
__device__ __forceinline__ void stcg_v4(Chunk* p, float a, float b, float c, int t) {
    asm volatile("st.global.cg.v4.b32 [%0], {%1,%2,%3,%4};"
                 :: "l"(p), "f"(a), "f"(b), "f"(c), "r"(t) : "memory");
}

__global__ void init_msgs_kernel() {
    int i = blockIdx.x * blockDim.x + threadIdx.x;
    int n = 2 * NCTA_ * 3 * NX_ * 4;            // total 32-bit words per array
    if (i < n) {
        ((int*)g_dnC)[i] = 0;
        ((int*)g_upC)[i] = 0;
    }
}

__global__ void __launch_bounds__(NX_, 1) wave_kernel(
    const float* __restrict__ xsrc,    // (B, NT)
    const float* __restrict__ vp,      // (NZ, NX)
    const float* __restrict__ vs,
    const float* __restrict__ rho,
    const int*   __restrict__ src_loc, // (B, 2)
    const int*   __restrict__ rec_loc, // (NREC, 2)
    float*       __restrict__ out)     // (NT, NREC, 2*B)
{
    const int c  = blockIdx.x;
    const int b  = c / NTILES_;
    const int tz = c % NTILES_;
    const int x  = threadIdx.x;
    const bool has_top = (tz > 0);
    const bool has_bot = (tz < NTILES_ - 1);
    const int xm = (x == 0) ? 0 : x - 1;              // clamp -> zero diff at edge
    const int xp = (x == NX_ - 1) ? NX_ - 1 : x + 1;

    __shared__ float s_vx [RZ_][NX_];
    __shared__ float s_vz [RZ_][NX_];
    __shared__ float s_txx[RZ_][NX_];
    __shared__ float s_txz[RZ_][NX_];
    // ghost staging rows (x-shifted reads of computed ghosts)
    __shared__ float sh_vxa1[NX_], sh_vza1[NX_], sh_txza1[NX_];
    __shared__ float sh_vxp1[NX_], sh_vzp1[NX_], sh_txxp1[NX_];

    // per-cell material coefficients (DT, 1/DH folded in)
    float bc[RZ_], cl2m[RZ_], clam[RZ_], cmu[RZ_];
    #pragma unroll
    for (int r = 0; r < RZ_; ++r) {
        int gi = (tz * RZ_ + r) * NX_ + x;
        float vpv = __ldg(&vp[gi]);
        float vsv = __ldg(&vs[gi]);
        float rh  = __ldg(&rho[gi]);
        float mu  = rh * vsv * vsv;
        float lam = rh * (vpv * vpv - 2.0f * vsv * vsv);
        bc[r]   = DT_ / (rh * DH_);
        cl2m[r] = (DT_ / DH_) * (lam + 2.0f * mu);
        clam[r] = (DT_ / DH_) * lam;
        cmu[r]  = (DT_ / DH_) * mu;
    }
    // ghost-row coefficients: a=z0-1, b=z0-2 (top), p=z1+1, q=z1+2 (bottom)
    float bA=0, bB=0, clamA=0, cl2mA=0, cmuA=0;
    float bP=0, bQ=0, clamP=0, cl2mP=0, cmuP=0;
    if (has_top) {
        int ga = (tz * RZ_ - 1) * NX_ + x;
        int gb = (tz * RZ_ - 2) * NX_ + x;
        float vpv = __ldg(&vp[ga]), vsv = __ldg(&vs[ga]), rh = __ldg(&rho[ga]);
        float mu  = rh * vsv * vsv;
        float lam = rh * (vpv * vpv - 2.0f * vsv * vsv);
        bA = DT_ / (rh * DH_);
        cl2mA = (DT_ / DH_) * (lam + 2.0f * mu);
        clamA = (DT_ / DH_) * lam;
        cmuA  = (DT_ / DH_) * mu;
        bB = DT_ / (__ldg(&rho[gb]) * DH_);
    }
    if (has_bot) {
        int gp = (tz * RZ_ + RZ_) * NX_ + x;
        int gq = (tz * RZ_ + RZ_ + 1) * NX_ + x;
        float vpv = __ldg(&vp[gp]), vsv = __ldg(&vs[gp]), rh = __ldg(&rho[gp]);
        float mu  = rh * vsv * vsv;
        float lam = rh * (vpv * vpv - 2.0f * vsv * vsv);
        bP = DT_ / (rh * DH_);
        cl2mP = (DT_ / DH_) * (lam + 2.0f * mu);
        clamP = (DT_ / DH_) * lam;
        cmuP  = (DT_ / DH_) * mu;
        bQ = DT_ / (__ldg(&rho[gq]) * DH_);
    }

    // wavefields, zero initial conditions
    float vx[RZ_]  = {}, vz[RZ_]  = {};
    float txx[RZ_] = {}, tzz[RZ_] = {}, txz[RZ_] = {};
    #pragma unroll
    for (int r = 0; r < RZ_; ++r) {
        s_vx[r][x] = 0.f; s_vz[r][x] = 0.f; s_txx[r][x] = 0.f; s_txz[r][x] = 0.f;
    }

    // source ownership
    const int ssz = src_loc[2 * b];
    const int ssx = src_loc[2 * b + 1];
    const bool is_src = ((ssz / RZ_) == tz) && (x == ssx);
    const int src_lr  = ssz % RZ_;
    const bool src_at_a = has_top && (ssz == tz * RZ_ - 1)  && (x == ssx);
    const bool src_at_p = has_bot && (ssz == tz * RZ_ + RZ_) && (x == ssx);

    // receiver ownership: thread index doubles as receiver index
    bool is_rec = false;
    int my_lrz = 0, my_rx = 0;
    if (x < NREC_) {
        int rz = rec_loc[2 * x];
        my_rx  = rec_loc[2 * x + 1];
        if ((rz / RZ_) == tz) { is_rec = true; my_lrz = rz % RZ_; }
    }

    const float2* xsrc2 = reinterpret_cast<const float2*>(xsrc + b * NT_);
    const Chunk* dn = has_top ? &g_dnC[0][c - 1][0][0] : nullptr;  // slot 0 base
    const Chunk* up = has_bot ? &g_upC[0][c + 1][0][0] : nullptr;
    const int slotStride = NCTA_ * 3 * NX_;     // Chunks per slot

    __syncthreads();

    for (int i = 1; i <= NIT_; ++i) {
        const int t1 = 2 * i - 1;
        const int t2 = 2 * i;
        const float2 wv = __ldg(&xsrc2[i - 1]);   // {xsrc[t1-1], xsrc[t2-1]}
        const float w1 = wv.x;
        const float w2 = wv.y;

        // ---- speculative FIRST-ATTEMPT message loads (top of iteration) ----
        const int want = i - 1;
        const int pr = want & 1;
        const Chunk* dnp_r = dn + pr * slotStride;
        const Chunk* upp_r = up + pr * slotStride;
        float t_vx=0, t_txx_x=0, t_txz_x=0, t_txx_xp=0, t_txz_xm=0;
        float t_vz=0, t_tzz=0, t_txz2=0, t_txz2_xm=0, t_vz2=0, t_tzz2=0;
        float b_vx=0, b_txx_x=0, b_txz_x=0, b_txx_xp=0, b_txz_xm=0;
        float b_vz=0, b_tzz=0, b_vx2=0, b_txx2=0, b_txz2=0, b_tzz2=0, b_txx2_xp=0;
        bool top_ok = !has_top, bot_ok = !has_bot;
        if (has_top) {
            int g0,g1,g2,g3,g4,g5; float u;
            ldcg_v4(dnp_r + 0*NX_ + x,  t_vx,   t_txx_x, t_txz_x,  g0);
            ldcg_v4(dnp_r + 0*NX_ + xm, u,      u,       t_txz_xm, g1);
            ldcg_v4(dnp_r + 0*NX_ + xp, u,      t_txx_xp,u,        g2);
            ldcg_v4(dnp_r + 1*NX_ + x,  t_vz,   t_tzz,   t_txz2,   g3);
            ldcg_v4(dnp_r + 1*NX_ + xm, u,      u,       t_txz2_xm,g4);
            ldcg_v4(dnp_r + 2*NX_ + x,  t_vz2,  t_tzz2,  u,        g5);
            top_ok = (g0==want)&(g1==want)&(g2==want)&(g3==want)&(g4==want)&(g5==want);
        }
        if (has_bot) {
            int g0,g1,g2,g3,g4,g5; float u;
            ldcg_v4(upp_r + 0*NX_ + x,  b_vx,   b_txx_x, b_txz_x,  g0);
            ldcg_v4(upp_r + 0*NX_ + xm, u,      u,       b_txz_xm, g1);
            ldcg_v4(upp_r + 0*NX_ + xp, u,      b_txx_xp,u,        g2);
            ldcg_v4(upp_r + 1*NX_ + x,  b_vz,   b_tzz,   b_vx2,    g3);
            ldcg_v4(upp_r + 2*NX_ + x,  b_txx2, b_txz2,  b_tzz2,   g4);
            ldcg_v4(upp_r + 2*NX_ + xp, b_txx2_xp, u,    u,        g5);
            bot_ok = (g0==want)&(g1==want)&(g2==want)&(g3==want)&(g4==want)&(g5==want);
        }

        // ---- V1 interior rows 1..RZ-2 (overlaps the speculative loads) ----
        #pragma unroll
        for (int r = 1; r < RZ_ - 1; ++r) {
            float txx_c = txx[r], txz_c = txz[r];
            vx[r] += bc[r] * ((s_txx[r][xp] - txx_c) + (txz_c - txz[r - 1]));
            vz[r] += bc[r] * ((txz_c - s_txz[r][xm]) + (tzz[r + 1] - tzz[r]));
        }
        // independent interior SMEM stores (more overlap)
        #pragma unroll
        for (int r = 1; r < RZ_ - 1; ++r) { s_vx[r][x] = vx[r]; s_vz[r][x] = vz[r]; }

        // ---- retry loop only if speculation missed ----
        while (!(top_ok && bot_ok)) {
            if (!top_ok) {
                int g0,g1,g2,g3,g4,g5; float u;
                ldcg_v4(dnp_r + 0*NX_ + x,  t_vx,   t_txx_x, t_txz_x,  g0);
                ldcg_v4(dnp_r + 0*NX_ + xm, u,      u,       t_txz_xm, g1);
                ldcg_v4(dnp_r + 0*NX_ + xp, u,      t_txx_xp,u,        g2);
                ldcg_v4(dnp_r + 1*NX_ + x,  t_vz,   t_tzz,   t_txz2,   g3);
                ldcg_v4(dnp_r + 1*NX_ + xm, u,      u,       t_txz2_xm,g4);
                ldcg_v4(dnp_r + 2*NX_ + x,  t_vz2,  t_tzz2,  u,        g5);
                top_ok = (g0==want)&(g1==want)&(g2==want)&(g3==want)&(g4==want)&(g5==want);
            }
            if (!bot_ok) {
                int g0,g1,g2,g3,g4,g5; float u;
                ldcg_v4(upp_r + 0*NX_ + x,  b_vx,   b_txx_x, b_txz_x,  g0);
                ldcg_v4(upp_r + 0*NX_ + xm, u,      u,       b_txz_xm, g1);
                ldcg_v4(upp_r + 0*NX_ + xp, u,      b_txx_xp,u,        g2);
                ldcg_v4(upp_r + 1*NX_ + x,  b_vz,   b_tzz,   b_vx2,    g3);
                ldcg_v4(upp_r + 2*NX_ + x,  b_txx2, b_txz2,  b_tzz2,   g4);
                ldcg_v4(upp_r + 2*NX_ + xp, b_txx2_xp, u,    u,        g5);
                bot_ok = (g0==want)&(g1==want)&(g2==want)&(g3==want)&(g4==want)&(g5==want);
            }
        }

        // ---- ghost t+1 velocities ----
        float vza1=0, vzb1=0, vxa1=0, vxp1=0, vxq1=0, vzp1=0;
        if (has_top) {
            vza1 = t_vz  + bA * ((t_txz_x  - t_txz_xm)  + (tzz[0] - t_tzz));
            vzb1 = t_vz2 + bB * ((t_txz2   - t_txz2_xm) + (t_tzz  - t_tzz2));
            vxa1 = t_vx  + bA * ((t_txx_xp - t_txx_x)   + (t_txz_x - t_txz2));
        }
        if (has_bot) {
            vxp1 = b_vx  + bP * ((b_txx_xp  - b_txx_x) + (b_txz_x - txz[RZ_ - 1]));
            vxq1 = b_vx2 + bQ * ((b_txx2_xp - b_txx2)  + (b_txz2  - b_txz_x));
            vzp1 = b_vz  + bP * ((b_txz_x   - b_txz_xm) + (b_tzz2 - b_tzz));
        }

        // ---- V1 edge rows 0 and RZ-1 ----
        {
            float txz_zm = has_top ? t_txz_x : txz[0];
            vx[0] += bc[0] * ((s_txx[0][xp] - txx[0]) + (txz[0] - txz_zm));
            vz[0] += bc[0] * ((txz[0] - s_txz[0][xm]) + (tzz[1] - tzz[0]));
            constexpr int r = RZ_ - 1;
            float tzz_zp = has_bot ? b_tzz : tzz[r];
            vx[r] += bc[r] * ((s_txx[r][xp] - txx[r]) + (txz[r] - txz[r - 1]));
            vz[r] += bc[r] * ((txz[r] - s_txz[r][xm]) + (tzz_zp - tzz[r]));
        }
        s_vx[0][x] = vx[0];             s_vz[0][x] = vz[0];
        s_vx[RZ_ - 1][x] = vx[RZ_ - 1]; s_vz[RZ_ - 1][x] = vz[RZ_ - 1];
        sh_vxa1[x] = vxa1; sh_vza1[x] = vza1;
        sh_vxp1[x] = vxp1; sh_vzp1[x] = vzp1;
        __syncthreads();   // (2)

        // record t1
        if (is_rec) {
            int base = (t1 - 1) * (NREC_ * 2 * B_) + x * (2 * B_);
            out[base + b]      = s_vx[my_lrz][my_rx];
            out[base + B_ + b] = s_vz[my_lrz][my_rx];
        }

        // ---- ghost t+1 edge stresses ----
        float tzza1=0, txza1=0, txxp1=0, tzzp1=0, txzp1=0;
        if (has_top) {
            tzza1 = t_tzz + clamA * (vxa1 - sh_vxa1[xm]) + cl2mA * (vza1 - vzb1);
            if (src_at_a) tzza1 += w1;
            txza1 = t_txz_x + cmuA * ((vx[0] - vxa1) + (sh_vza1[xp] - vza1));
        }
        if (has_bot) {
            float dvx_p = vxp1 - sh_vxp1[xm];
            float dvz_p = vzp1 - vz[RZ_ - 1];
            txxp1 = b_txx_x + cl2mP * dvx_p + clamP * dvz_p;
            tzzp1 = b_tzz   + clamP * dvx_p + cl2mP * dvz_p;
            if (src_at_p) { txxp1 += w1; tzzp1 += w1; }
            txzp1 = b_txz_x + cmuP * ((vxq1 - vxp1) + (sh_vzp1[xp] - vzp1));
        }

        // ------------------ S1 ------------------
        #pragma unroll
        for (int r = 0; r < RZ_; ++r) {
            float vx_c = vx[r], vz_c = vz[r];
            float vz_zm = (r > 0) ? vz[r - 1] : (has_top ? vza1 : vz_c);
            float vx_zp = (r < RZ_ - 1) ? vx[r + 1] : (has_bot ? vxp1 : vx_c);
            float dvx = vx_c - s_vx[r][xm];
            float dvz = vz_c - vz_zm;
            txx[r] += cl2m[r] * dvx + clam[r] * dvz;
            tzz[r] += clam[r] * dvx + cl2m[r] * dvz;
            txz[r] += cmu[r] * ((vx_zp - vx_c) + (s_vz[r][xp] - vz_c));
        }
        if (is_src) {
            #pragma unroll
            for (int r = 0; r < RZ_; ++r)
                if (r == src_lr) { txx[r] += w1; tzz[r] += w1; }
        }
        #pragma unroll
        for (int r = 0; r < RZ_; ++r) { s_txx[r][x] = txx[r]; s_txz[r][x] = txz[r]; }
        sh_txza1[x] = txza1; sh_txxp1[x] = txxp1;
        __syncthreads();   // (3)

        // ---- ghost t+2 edge velocities ----
        float vza2 = 0, vxp2 = 0;
        if (has_top)
            vza2 = vza1 + bA * ((txza1 - sh_txza1[xm]) + (tzz[0] - tzza1));
        if (has_bot)
            vxp2 = vxp1 + bP * ((sh_txxp1[xp] - txxp1) + (txzp1 - txz[RZ_ - 1]));

        // ------------------ V2 ------------------
        #pragma unroll
        for (int r = 0; r < RZ_; ++r) {
            float txx_c = txx[r], txz_c = txz[r];
            float txz_zm = (r > 0) ? txz[r - 1] : (has_top ? txza1 : txz_c);
            float tzz_zp = (r < RZ_ - 1) ? tzz[r + 1] : (has_bot ? tzzp1 : tzz[r]);
            vx[r] += bc[r] * ((s_txx[r][xp] - txx_c) + (txz_c - txz_zm));
            vz[r] += bc[r] * ((txz_c - s_txz[r][xm]) + (tzz_zp - tzz[r]));
        }
        #pragma unroll
        for (int r = 0; r < RZ_; ++r) { s_vx[r][x] = vx[r]; s_vz[r][x] = vz[r]; }
        __syncthreads();   // (4)

        // ---- S2 apron rows {0,1,RZ-2,RZ-1} first, then per-lane publish ----
        #pragma unroll
        for (int rr = 0; rr < 4; ++rr) {
            const int r = (rr < 2) ? rr : RZ_ - 4 + rr;   // 0,1,RZ-2,RZ-1
            float vx_c = vx[r], vz_c = vz[r];
            float vz_zm = (r > 0) ? vz[r - 1] : (has_top ? vza2 : vz_c);
            float vx_zp = (r < RZ_ - 1) ? vx[r + 1] : (has_bot ? vxp2 : vx_c);
            float dvx = vx_c - s_vx[r][xm];
            float dvz = vz_c - vz_zm;
            txx[r] += cl2m[r] * dvx + clam[r] * dvz;
            tzz[r] += clam[r] * dvx + cl2m[r] * dvz;
            txz[r] += cmu[r] * ((vx_zp - vx_c) + (s_vz[r][xp] - vz_c));
            if (is_src && r == src_lr) { txx[r] += w2; tzz[r] += w2; }
        }
        // publish t+2 apron, tag = i (per-lane, no barrier, no flag)
        {
            const int pw = i & 1;
            Chunk* dnp = &g_dnC[pw][c][0][0];
            stcg_v4(dnp + 0*NX_ + x, vx[RZ_-1], txx[RZ_-1], txz[RZ_-1], i);
            stcg_v4(dnp + 1*NX_ + x, vz[RZ_-1], tzz[RZ_-1], txz[RZ_-2], i);
            stcg_v4(dnp + 2*NX_ + x, vz[RZ_-2], tzz[RZ_-2], 0.f,        i);
            Chunk* upp = &g_upC[pw][c][0][0];
            stcg_v4(upp + 0*NX_ + x, vx[0], txx[0], txz[0], i);
            stcg_v4(upp + 1*NX_ + x, vz[0], tzz[0], vx[1],  i);
            stcg_v4(upp + 2*NX_ + x, txx[1], txz[1], tzz[1], i);
        }

        // record t2 (s_vx/s_vz valid since sync 4; S2 doesn't touch them)
        if (is_rec) {
            int base = (t2 - 1) * (NREC_ * 2 * B_) + x * (2 * B_);
            out[base + b]      = s_vx[my_lrz][my_rx];
            out[base + B_ + b] = s_vz[my_lrz][my_rx];
        }

        // ---- S2 interior rows 2..RZ-3 (off the inter-CTA critical path) ----
        #pragma unroll
        for (int r = 2; r < RZ_ - 2; ++r) {
            float vx_c = vx[r], vz_c = vz[r];
            float dvx = vx_c - s_vx[r][xm];
            float dvz = vz_c - vz[r - 1];
            txx[r] += cl2m[r] * dvx + clam[r] * dvz;
            tzz[r] += clam[r] * dvx + cl2m[r] * dvz;
            txz[r] += cmu[r] * ((vx[r + 1] - vx_c) + (s_vz[r][xp] - vz_c));
            if (is_src && r == src_lr) { txx[r] += w2; tzz[r] += w2; }
        }
        #pragma unroll
        for (int r = 0; r < RZ_; ++r) { s_txx[r][x] = txx[r]; s_txz[r][x] = txz[r]; }
        __syncthreads();   // (6) — next iter's V1 reads s_txx/s_txz
    }
}

extern "C" void kernel_launch(void* const* d_in, const int* in_sizes, int n_in,
                              void* d_out, int out_size) {
    const float* x   = (const float*)d_in[0];
    const float* vp  = (const float*)d_in[1];
    const float* vs  = (const float*)d_in[2];
    const float* rho = (const float*)d_in[3];
    const int* src   = (const int*)d_in[4];
    const int* rec   = (const int*)d_in[5];
    float* out = (float*)d_out;

    // re-zero message slots (tags -> 0) so every graph replay is identical
    int n = 2 * NCTA_ * 3 * NX_ * 4;
    init_msgs_kernel<<<(n + 255) / 256, 256>>>();
    wave_kernel<<<NCTA_, NX_>>>(x, vp, vs, rho, src, rec, out);
}

// round 16
// speedup vs baseline: 1.6947x; 1.2197x over previous
#include <cuda_runtime.h>

// ---------------------------------------------------------------------------
// 2-D elastic staggered-grid FDTD, persistent kernel, k=2 time blocking.
// R8 structure (the proven optimum of this session): one thread per column,
// 6 rows of all 5 fields in registers, SMEM x-neighbor mirrors, 4 barriers
// per 2-step iteration, and a TAGGED-CHUNK neighbor exchange: message
// payloads and the iteration tag travel in the same 16-byte
// st/ld.global.cg.v4, so the exchange costs ONE L2 round trip with no flags,
// no acquire/release, and no poll-broadcast barrier.
//
// Chunk layout per column x (slot = iter parity):
//   dn (c -> c+1, c's LAST rows):  A={vx5,txx5,txz5,tag} B={vz5,tzz5,txz4,tag}
//                                  C={vz4,tzz4,0,tag}
//   up (c -> c-1, c's FIRST rows): D={vx0,txx0,txz0,tag} E={vz0,tzz0,vx1,tag}
//                                  F={txx1,txz1,tzz1,tag}
//
// Race-safety: tag==i-1 equality poll; producer overwrite of slot i&1 cannot
// race a lagging reader because the producer's entry into iter i data-depends
// (through the neighbor's published values) on the neighbor having consumed
// the i-2 contents of that slot. 16B v4 accesses are single L2 transactions
// on sm_103a, so tag and payload are atomic per chunk.
//
// Output layout (reference): (NT, NREC, 2*B):
//   out[t*NREC*8 + r*8 + comp*4 + b], comp 0 = vx, comp 1 = vz.
// ---------------------------------------------------------------------------

namespace {
constexpr int B_    = 4;
constexpr int NT_   = 256;
constexpr int NZ_   = 192;
constexpr int NX_   = 192;
constexpr int NREC_ = 128;
constexpr int RZ_   = 6;                 // rows per tile
constexpr int NTILES_ = NZ_ / RZ_;       // 32
constexpr int NCTA_   = B_ * NTILES_;    // 128 (< 148 SMs -> all co-resident)
constexpr int NIT_    = NT_ / 2;         // 128 iterations
constexpr float DT_ = 0.001f;
constexpr float DH_ = 10.0f;
}

struct __align__(16) Chunk { float a, b, c; int tag; };

// double-buffered tagged message chunks: [slot][cta][chunk 0..2][x]
__device__ Chunk g_dnC[2][NCTA_][3][NX_];
__device__ Chunk g_upC[2][NCTA_][3][NX_];

__device__ __forceinline__ void ldcg_v4(const Chunk* p, float& a, float& b,
                                        float& c, int& t) {
    asm volatile("ld.global.cg.v4.b32 {%0,%1,%2,%3}, [%4];"
                 : "=f"(a), "=f"(b), "=f"(c), "=r"(t) : "l"(p));
}
__device__ __forceinline__ void stcg_v4(Chunk* p, float a, float b, float c, int t) {
    asm volatile("st.global.cg.v4.b32 [%0], {%1,%2,%3,%4};"
                 :: "l"(p), "f"(a), "f"(b), "f"(c), "r"(t) : "memory");
}

__global__ void init_msgs_kernel() {
    int i = blockIdx.x * blockDim.x + threadIdx.x;
    int n = 2 * NCTA_ * 3 * NX_ * 4;            // total 32-bit words per array
    if (i < n) {
        ((int*)g_dnC)[i] = 0;
        ((int*)g_upC)[i] = 0;
    }
}

__global__ void __launch_bounds__(NX_, 1) wave_kernel(
    const float* __restrict__ xsrc,    // (B, NT)
    const float* __restrict__ vp,      // (NZ, NX)
    const float* __restrict__ vs,
    const float* __restrict__ rho,
    const int*   __restrict__ src_loc, // (B, 2)
    const int*   __restrict__ rec_loc, // (NREC, 2)
    float*       __restrict__ out)     // (NT, NREC, 2*B)
{
    const int c  = blockIdx.x;
    const int b  = c / NTILES_;
    const int tz = c % NTILES_;
    const int x  = threadIdx.x;
    const bool has_top = (tz > 0);
    const bool has_bot = (tz < NTILES_ - 1);
    const int xm = (x == 0) ? 0 : x - 1;              // clamp -> zero diff at edge
    const int xp = (x == NX_ - 1) ? NX_ - 1 : x + 1;

    __shared__ float s_vx [RZ_][NX_];
    __shared__ float s_vz [RZ_][NX_];
    __shared__ float s_txx[RZ_][NX_];
    __shared__ float s_txz[RZ_][NX_];
    // ghost staging rows (x-shifted reads of computed ghosts)
    __shared__ float sh_vxa1[NX_], sh_vza1[NX_], sh_txza1[NX_];
    __shared__ float sh_vxp1[NX_], sh_vzp1[NX_], sh_txxp1[NX_];

    // per-cell material coefficients (DT, 1/DH folded in)
    float bc[RZ_], cl2m[RZ_], clam[RZ_], cmu[RZ_];
    #pragma unroll
    for (int r = 0; r < RZ_; ++r) {
        int gi = (tz * RZ_ + r) * NX_ + x;
        float vpv = __ldg(&vp[gi]);
        float vsv = __ldg(&vs[gi]);
        float rh  = __ldg(&rho[gi]);
        float mu  = rh * vsv * vsv;
        float lam = rh * (vpv * vpv - 2.0f * vsv * vsv);
        bc[r]   = DT_ / (rh * DH_);
        cl2m[r] = (DT_ / DH_) * (lam + 2.0f * mu);
        clam[r] = (DT_ / DH_) * lam;
        cmu[r]  = (DT_ / DH_) * mu;
    }
    // ghost-row coefficients: a=z0-1, b=z0-2 (top), p=z1+1, q=z1+2 (bottom)
    float bA=0, bB=0, clamA=0, cl2mA=0, cmuA=0;
    float bP=0, bQ=0, clamP=0, cl2mP=0, cmuP=0;
    if (has_top) {
        int ga = (tz * RZ_ - 1) * NX_ + x;
        int gb = (tz * RZ_ - 2) * NX_ + x;
        float vpv = __ldg(&vp[ga]), vsv = __ldg(&vs[ga]), rh = __ldg(&rho[ga]);
        float mu  = rh * vsv * vsv;
        float lam = rh * (vpv * vpv - 2.0f * vsv * vsv);
        bA = DT_ / (rh * DH_);
        cl2mA = (DT_ / DH_) * (lam + 2.0f * mu);
        clamA = (DT_ / DH_) * lam;
        cmuA  = (DT_ / DH_) * mu;
        bB = DT_ / (__ldg(&rho[gb]) * DH_);
    }
    if (has_bot) {
        int gp = (tz * RZ_ + RZ_) * NX_ + x;
        int gq = (tz * RZ_ + RZ_ + 1) * NX_ + x;
        float vpv = __ldg(&vp[gp]), vsv = __ldg(&vs[gp]), rh = __ldg(&rho[gp]);
        float mu  = rh * vsv * vsv;
        float lam = rh * (vpv * vpv - 2.0f * vsv * vsv);
        bP = DT_ / (rh * DH_);
        cl2mP = (DT_ / DH_) * (lam + 2.0f * mu);
        clamP = (DT_ / DH_) * lam;
        cmuP  = (DT_ / DH_) * mu;
        bQ = DT_ / (__ldg(&rho[gq]) * DH_);
    }

    // wavefields, zero initial conditions
    float vx[RZ_]  = {}, vz[RZ_]  = {};
    float txx[RZ_] = {}, tzz[RZ_] = {}, txz[RZ_] = {};
    #pragma unroll
    for (int r = 0; r < RZ_; ++r) {
        s_vx[r][x] = 0.f; s_vz[r][x] = 0.f; s_txx[r][x] = 0.f; s_txz[r][x] = 0.f;
    }

    // source ownership
    const int ssz = src_loc[2 * b];
    const int ssx = src_loc[2 * b + 1];
    const bool is_src = ((ssz / RZ_) == tz) && (x == ssx);
    const int src_lr  = ssz % RZ_;
    const bool src_at_a = has_top && (ssz == tz * RZ_ - 1)  && (x == ssx);
    const bool src_at_p = has_bot && (ssz == tz * RZ_ + RZ_) && (x == ssx);

    // receiver ownership: thread index doubles as receiver index
    bool is_rec = false;
    int my_lrz = 0, my_rx = 0;
    if (x < NREC_) {
        int rz = rec_loc[2 * x];
        my_rx  = rec_loc[2 * x + 1];
        if ((rz / RZ_) == tz) { is_rec = true; my_lrz = rz % RZ_; }
    }

    __syncthreads();

    for (int i = 1; i <= NIT_; ++i) {
        const int t1 = 2 * i - 1;
        const int t2 = 2 * i;
        const float w1 = __ldg(&xsrc[b * NT_ + (t1 - 1)]);
        const float w2 = __ldg(&xsrc[b * NT_ + (t2 - 1)]);

        // ---- V1 interior rows 1..RZ-2 (no message dependence) ----
        #pragma unroll
        for (int r = 1; r < RZ_ - 1; ++r) {
            float txx_c = txx[r], txz_c = txz[r];
            vx[r] += bc[r] * ((s_txx[r][xp] - txx_c) + (txz_c - txz[r - 1]));
            vz[r] += bc[r] * ((txz_c - s_txz[r][xm]) + (tzz[r + 1] - tzz[r]));
        }

        // ---- per-lane tagged message poll (ONE RTT, no barrier) ----
        const int want = i - 1;
        const int pr = want & 1;
        // top side values (from c-1's dn)
        float t_vx=0, t_txx_x=0, t_txz_x=0, t_txx_xp=0, t_txz_xm=0;
        float t_vz=0, t_tzz=0, t_txz2=0, t_txz2_xm=0, t_vz2=0, t_tzz2=0;
        // bottom side values (from c+1's up)
        float b_vx=0, b_txx_x=0, b_txz_x=0, b_txx_xp=0, b_txz_xm=0;
        float b_vz=0, b_tzz=0, b_vx2=0, b_txx2=0, b_txz2=0, b_tzz2=0, b_txx2_xp=0;
        {
            const Chunk* dn = has_top ? &g_dnC[pr][c - 1][0][0] : nullptr;
            const Chunk* up = has_bot ? &g_upC[pr][c + 1][0][0] : nullptr;
            bool top_ok = !has_top, bot_ok = !has_bot;
            do {
                if (!top_ok) {
                    int g0,g1,g2,g3,g4,g5; float u;
                    ldcg_v4(dn + 0*NX_ + x,  t_vx,   t_txx_x, t_txz_x,  g0);
                    ldcg_v4(dn + 0*NX_ + xm, u,      u,       t_txz_xm, g1);
                    ldcg_v4(dn + 0*NX_ + xp, u,      t_txx_xp,u,        g2);
                    ldcg_v4(dn + 1*NX_ + x,  t_vz,   t_tzz,   t_txz2,   g3);
                    ldcg_v4(dn + 1*NX_ + xm, u,      u,       t_txz2_xm,g4);
                    ldcg_v4(dn + 2*NX_ + x,  t_vz2,  t_tzz2,  u,        g5);
                    top_ok = (g0==want)&(g1==want)&(g2==want)&(g3==want)&(g4==want)&(g5==want);
                }
                if (!bot_ok) {
                    int g0,g1,g2,g3,g4,g5; float u;
                    ldcg_v4(up + 0*NX_ + x,  b_vx,   b_txx_x, b_txz_x,  g0);
                    ldcg_v4(up + 0*NX_ + xm, u,      u,       b_txz_xm, g1);
                    ldcg_v4(up + 0*NX_ + xp, u,      b_txx_xp,u,        g2);
                    ldcg_v4(up + 1*NX_ + x,  b_vz,   b_tzz,   b_vx2,    g3);
                    ldcg_v4(up + 2*NX_ + x,  b_txx2, b_txz2,  b_tzz2,   g4);
                    ldcg_v4(up + 2*NX_ + xp, b_txx2_xp, u,    u,        g5);
                    bot_ok = (g0==want)&(g1==want)&(g2==want)&(g3==want)&(g4==want)&(g5==want);
                }
            } while (!(top_ok && bot_ok));
        }
        // overlap: independent interior SMEM stores
        #pragma unroll
        for (int r = 1; r < RZ_ - 1; ++r) { s_vx[r][x] = vx[r]; s_vz[r][x] = vz[r]; }

        // ---- ghost t+1 velocities ----
        float vza1=0, vzb1=0, vxa1=0, vxp1=0, vxq1=0, vzp1=0;
        if (has_top) {
            vza1 = t_vz  + bA * ((t_txz_x  - t_txz_xm)  + (tzz[0] - t_tzz));
            vzb1 = t_vz2 + bB * ((t_txz2   - t_txz2_xm) + (t_tzz  - t_tzz2));
            vxa1 = t_vx  + bA * ((t_txx_xp - t_txx_x)   + (t_txz_x - t_txz2));
        }
        if (has_bot) {
            vxp1 = b_vx  + bP * ((b_txx_xp  - b_txx_x) + (b_txz_x - txz[RZ_ - 1]));
            vxq1 = b_vx2 + bQ * ((b_txx2_xp - b_txx2)  + (b_txz2  - b_txz_x));
            vzp1 = b_vz  + bP * ((b_txz_x   - b_txz_xm) + (b_tzz2 - b_tzz));
        }

        // ---- V1 edge rows 0 and RZ-1 ----
        {
            float txz_zm = has_top ? t_txz_x : txz[0];
            vx[0] += bc[0] * ((s_txx[0][xp] - txx[0]) + (txz[0] - txz_zm));
            vz[0] += bc[0] * ((txz[0] - s_txz[0][xm]) + (tzz[1] - tzz[0]));
            constexpr int r = RZ_ - 1;
            float tzz_zp = has_bot ? b_tzz : tzz[r];
            vx[r] += bc[r] * ((s_txx[r][xp] - txx[r]) + (txz[r] - txz[r - 1]));
            vz[r] += bc[r] * ((txz[r] - s_txz[r][xm]) + (tzz_zp - tzz[r]));
        }
        s_vx[0][x] = vx[0];             s_vz[0][x] = vz[0];
        s_vx[RZ_ - 1][x] = vx[RZ_ - 1]; s_vz[RZ_ - 1][x] = vz[RZ_ - 1];
        sh_vxa1[x] = vxa1; sh_vza1[x] = vza1;
        sh_vxp1[x] = vxp1; sh_vzp1[x] = vzp1;
        __syncthreads();   // (2)

        // record t1
        if (is_rec) {
            int base = (t1 - 1) * (NREC_ * 2 * B_) + x * (2 * B_);
            out[base + b]      = s_vx[my_lrz][my_rx];
            out[base + B_ + b] = s_vz[my_lrz][my_rx];
        }

        // ---- ghost t+1 edge stresses ----
        float tzza1=0, txza1=0, txxp1=0, tzzp1=0, txzp1=0;
        if (has_top) {
            tzza1 = t_tzz + clamA * (vxa1 - sh_vxa1[xm]) + cl2mA * (vza1 - vzb1);
            if (src_at_a) tzza1 += w1;
            txza1 = t_txz_x + cmuA * ((vx[0] - vxa1) + (sh_vza1[xp] - vza1));
        }
        if (has_bot) {
            float dvx_p = vxp1 - sh_vxp1[xm];
            float dvz_p = vzp1 - vz[RZ_ - 1];
            txxp1 = b_txx_x + cl2mP * dvx_p + clamP * dvz_p;
            tzzp1 = b_tzz   + clamP * dvx_p + cl2mP * dvz_p;
            if (src_at_p) { txxp1 += w1; tzzp1 += w1; }
            txzp1 = b_txz_x + cmuP * ((vxq1 - vxp1) + (sh_vzp1[xp] - vzp1));
        }

        // ------------------ S1 ------------------
        #pragma unroll
        for (int r = 0; r < RZ_; ++r) {
            float vx_c = vx[r], vz_c = vz[r];
            float vz_zm = (r > 0) ? vz[r - 1] : (has_top ? vza1 : vz_c);
            float vx_zp = (r < RZ_ - 1) ? vx[r + 1] : (has_bot ? vxp1 : vx_c);
            float dvx = vx_c - s_vx[r][xm];
            float dvz = vz_c - vz_zm;
            txx[r] += cl2m[r] * dvx + clam[r] * dvz;
            tzz[r] += clam[r] * dvx + cl2m[r] * dvz;
            txz[r] += cmu[r] * ((vx_zp - vx_c) + (s_vz[r][xp] - vz_c));
        }
        if (is_src) {
            #pragma unroll
            for (int r = 0; r < RZ_; ++r)
                if (r == src_lr) { txx[r] += w1; tzz[r] += w1; }
        }
        #pragma unroll
        for (int r = 0; r < RZ_; ++r) { s_txx[r][x] = txx[r]; s_txz[r][x] = txz[r]; }
        sh_txza1[x] = txza1; sh_txxp1[x] = txxp1;
        __syncthreads();   // (3)

        // ---- ghost t+2 edge velocities ----
        float vza2 = 0, vxp2 = 0;
        if (has_top)
            vza2 = vza1 + bA * ((txza1 - sh_txza1[xm]) + (tzz[0] - tzza1));
        if (has_bot)
            vxp2 = vxp1 + bP * ((sh_txxp1[xp] - txxp1) + (txzp1 - txz[RZ_ - 1]));

        // ------------------ V2 ------------------
        #pragma unroll
        for (int r = 0; r < RZ_; ++r) {
            float txx_c = txx[r], txz_c = txz[r];
            float txz_zm = (r > 0) ? txz[r - 1] : (has_top ? txza1 : txz_c);
            float tzz_zp = (r < RZ_ - 1) ? tzz[r + 1] : (has_bot ? tzzp1 : tzz[r]);
            vx[r] += bc[r] * ((s_txx[r][xp] - txx_c) + (txz_c - txz_zm));
            vz[r] += bc[r] * ((txz_c - s_txz[r][xm]) + (tzz_zp - tzz[r]));
        }
        #pragma unroll
        for (int r = 0; r < RZ_; ++r) { s_vx[r][x] = vx[r]; s_vz[r][x] = vz[r]; }
        __syncthreads();   // (4)

        // ---- S2 apron rows {0,1,RZ-2,RZ-1} first, then per-lane publish ----
        #pragma unroll
        for (int rr = 0; rr < 4; ++rr) {
            const int r = (rr < 2) ? rr : RZ_ - 4 + rr;   // 0,1,RZ-2,RZ-1
            float vx_c = vx[r], vz_c = vz[r];
            float vz_zm = (r > 0) ? vz[r - 1] : (has_top ? vza2 : vz_c);
            float vx_zp = (r < RZ_ - 1) ? vx[r + 1] : (has_bot ? vxp2 : vx_c);
            float dvx = vx_c - s_vx[r][xm];
            float dvz = vz_c - vz_zm;
            txx[r] += cl2m[r] * dvx + clam[r] * dvz;
            tzz[r] += clam[r] * dvx + cl2m[r] * dvz;
            txz[r] += cmu[r] * ((vx_zp - vx_c) + (s_vz[r][xp] - vz_c));
            if (is_src && r == src_lr) { txx[r] += w2; tzz[r] += w2; }
        }
        // publish t+2 apron, tag = i (per-lane, no barrier, no flag)
        {
            const int pw = i & 1;
            Chunk* dnp = &g_dnC[pw][c][0][0];
            stcg_v4(dnp + 0*NX_ + x, vx[RZ_-1], txx[RZ_-1], txz[RZ_-1], i);
            stcg_v4(dnp + 1*NX_ + x, vz[RZ_-1], tzz[RZ_-1], txz[RZ_-2], i);
            stcg_v4(dnp + 2*NX_ + x, vz[RZ_-2], tzz[RZ_-2], 0.f,        i);
            Chunk* upp = &g_upC[pw][c][0][0];
            stcg_v4(upp + 0*NX_ + x, vx[0], txx[0], txz[0], i);
            stcg_v4(upp + 1*NX_ + x, vz[0], tzz[0], vx[1],  i);
            stcg_v4(upp + 2*NX_ + x, txx[1], txz[1], tzz[1], i);
        }

        // record t2 (s_vx/s_vz valid since sync 4; S2 doesn't touch them)
        if (is_rec) {
            int base = (t2 - 1) * (NREC_ * 2 * B_) + x * (2 * B_);
            out[base + b]      = s_vx[my_lrz][my_rx];
            out[base + B_ + b] = s_vz[my_lrz][my_rx];
        }

        // ---- S2 interior rows 2..RZ-3 (off the inter-CTA critical path) ----
        #pragma unroll
        for (int r = 2; r < RZ_ - 2; ++r) {
            float vx_c = vx[r], vz_c = vz[r];
            float dvx = vx_c - s_vx[r][xm];
            float dvz = vz_c - vz[r - 1];
            txx[r] += cl2m[r] * dvx + clam[r] * dvz;
            tzz[r] += clam[r] * dvx + cl2m[r] * dvz;
            txz[r] += cmu[r] * ((vx[r + 1] - vx_c) + (s_vz[r][xp] - vz_c));
            if (is_src && r == src_lr) { txx[r] += w2; tzz[r] += w2; }
        }
        #pragma unroll
        for (int r = 0; r < RZ_; ++r) { s_txx[r][x] = txx[r]; s_txz[r][x] = txz[r]; }
        __syncthreads();   // (6) — next iter's V1 reads s_txx/s_txz
    }
}

extern "C" void kernel_launch(void* const* d_in, const int* in_sizes, int n_in,
                              void* d_out, int out_size) {
    const float* x   = (const float*)d_in[0];
    const float* vp  = (const float*)d_in[1];
    const float* vs  = (const float*)d_in[2];
    const float* rho = (const float*)d_in[3];
    const int* src   = (const int*)d_in[4];
    const int* rec   = (const int*)d_in[5];
    float* out = (float*)d_out;

    // re-zero message slots (tags -> 0) so every graph replay is identical
    int n = 2 * NCTA_ * 3 * NX_ * 4;
    init_msgs_kernel<<<(n + 255) / 256, 256>>>();
    wave_kernel<<<NCTA_, NX_>>>(x, vp, vs, rho, src, rec, out);
}

// round 17
// speedup vs baseline: 1.7057x; 1.0065x over previous
#include <cuda_runtime.h>

// ---------------------------------------------------------------------------
// 2-D elastic staggered-grid FDTD, persistent kernel, k=2 time blocking.
// R8 structure (the proven optimum of this session): one thread per column,
// 6 rows of all 5 fields in registers, SMEM x-neighbor mirrors, 4 barriers
// per 2-step iteration, and a TAGGED-CHUNK neighbor exchange: message
// payloads and the iteration tag travel in the same 16-byte
// st/ld.global.cg.v4, so the exchange costs ONE L2 round trip with no flags,
// no acquire/release, and no poll-broadcast barrier.
//
// Chunk layout per column x (slot = iter parity):
//   dn (c -> c+1, c's LAST rows):  A={vx5,txx5,txz5,tag} B={vz5,tzz5,txz4,tag}
//                                  C={vz4,tzz4,0,tag}
//   up (c -> c-1, c's FIRST rows): D={vx0,txx0,txz0,tag} E={vz0,tzz0,vx1,tag}
//                                  F={txx1,txz1,tzz1,tag}
//
// Race-safety: tag==i-1 equality poll; producer overwrite of slot i&1 cannot
// race a lagging reader because the producer's entry into iter i data-depends
// (through the neighbor's published values) on the neighbor having consumed
// the i-2 contents of that slot. 16B v4 accesses are single L2 transactions
// on sm_103a, so tag and payload are atomic per chunk.
//
// Output layout (reference): (NT, NREC, 2*B):
//   out[t*NREC*8 + r*8 + comp*4 + b], comp 0 = vx, comp 1 = vz.
// ---------------------------------------------------------------------------

namespace {
constexpr int B_    = 4;
constexpr int NT_   = 256;
constexpr int NZ_   = 192;
constexpr int NX_   = 192;
constexpr int NREC_ = 128;
constexpr int RZ_   = 6;                 // rows per tile
constexpr int NTILES_ = NZ_ / RZ_;       // 32
constexpr int NCTA_   = B_ * NTILES_;    // 128 (< 148 SMs -> all co-resident)
constexpr int NIT_    = NT_ / 2;         // 128 iterations
constexpr float DT_ = 0.001f;
constexpr float DH_ = 10.0f;
}

struct __align__(16) Chunk { float a, b, c; int tag; };

// double-buffered tagged message chunks: [slot][cta][chunk 0..2][x]
__device__ Chunk g_dnC[2][NCTA_][3][NX_];
__device__ Chunk g_upC[2][NCTA_][3][NX_];

__device__ __forceinline__ void ldcg_v4(const Chunk* p, float& a, float& b,
                                        float& c, int& t) {
    asm volatile("ld.global.cg.v4.b32 {%0,%1,%2,%3}, [%4];"
                 : "=f"(a), "=f"(b), "=f"(c), "=r"(t) : "l"(p));
}
__device__ __forceinline__ void stcg_v4(Chunk* p, float a, float b, float c, int t) {
    asm volatile("st.global.cg.v4.b32 [%0], {%1,%2,%3,%4};"
                 :: "l"(p), "f"(a), "f"(b), "f"(c), "r"(t) : "memory");
}

__global__ void init_msgs_kernel() {
    int i = blockIdx.x * blockDim.x + threadIdx.x;
    int n = 2 * NCTA_ * 3 * NX_ * 4;            // total 32-bit words per array
    if (i < n) {
        ((int*)g_dnC)[i] = 0;
        ((int*)g_upC)[i] = 0;
    }
}

__global__ void __launch_bounds__(NX_, 1) wave_kernel(
    const float* __restrict__ xsrc,    // (B, NT)
    const float* __restrict__ vp,      // (NZ, NX)
    const float* __restrict__ vs,
    const float* __restrict__ rho,
    const int*   __restrict__ src_loc, // (B, 2)
    const int*   __restrict__ rec_loc, // (NREC, 2)
    float*       __restrict__ out)     // (NT, NREC, 2*B)
{
    const int c  = blockIdx.x;
    const int b  = c / NTILES_;
    const int tz = c % NTILES_;
    const int x  = threadIdx.x;
    const bool has_top = (tz > 0);
    const bool has_bot = (tz < NTILES_ - 1);
    const int xm = (x == 0) ? 0 : x - 1;              // clamp -> zero diff at edge
    const int xp = (x == NX_ - 1) ? NX_ - 1 : x + 1;

    __shared__ float s_vx [RZ_][NX_];
    __shared__ float s_vz [RZ_][NX_];
    __shared__ float s_txx[RZ_][NX_];
    __shared__ float s_txz[RZ_][NX_];
    // ghost staging rows (x-shifted reads of computed ghosts)
    __shared__ float sh_vxa1[NX_], sh_vza1[NX_], sh_txza1[NX_];
    __shared__ float sh_vxp1[NX_], sh_vzp1[NX_], sh_txxp1[NX_];

    // per-cell material coefficients (DT, 1/DH folded in)
    float bc[RZ_], cl2m[RZ_], clam[RZ_], cmu[RZ_];
    #pragma unroll
    for (int r = 0; r < RZ_; ++r) {
        int gi = (tz * RZ_ + r) * NX_ + x;
        float vpv = __ldg(&vp[gi]);
        float vsv = __ldg(&vs[gi]);
        float rh  = __ldg(&rho[gi]);
        float mu  = rh * vsv * vsv;
        float lam = rh * (vpv * vpv - 2.0f * vsv * vsv);
        bc[r]   = DT_ / (rh * DH_);
        cl2m[r] = (DT_ / DH_) * (lam + 2.0f * mu);
        clam[r] = (DT_ / DH_) * lam;
        cmu[r]  = (DT_ / DH_) * mu;
    }
    // ghost-row coefficients: a=z0-1, b=z0-2 (top), p=z1+1, q=z1+2 (bottom)
    float bA=0, bB=0, clamA=0, cl2mA=0, cmuA=0;
    float bP=0, bQ=0, clamP=0, cl2mP=0, cmuP=0;
    if (has_top) {
        int ga = (tz * RZ_ - 1) * NX_ + x;
        int gb = (tz * RZ_ - 2) * NX_ + x;
        float vpv = __ldg(&vp[ga]), vsv = __ldg(&vs[ga]), rh = __ldg(&rho[ga]);
        float mu  = rh * vsv * vsv;
        float lam = rh * (vpv * vpv - 2.0f * vsv * vsv);
        bA = DT_ / (rh * DH_);
        cl2mA = (DT_ / DH_) * (lam + 2.0f * mu);
        clamA = (DT_ / DH_) * lam;
        cmuA  = (DT_ / DH_) * mu;
        bB = DT_ / (__ldg(&rho[gb]) * DH_);
    }
    if (has_bot) {
        int gp = (tz * RZ_ + RZ_) * NX_ + x;
        int gq = (tz * RZ_ + RZ_ + 1) * NX_ + x;
        float vpv = __ldg(&vp[gp]), vsv = __ldg(&vs[gp]), rh = __ldg(&rho[gp]);
        float mu  = rh * vsv * vsv;
        float lam = rh * (vpv * vpv - 2.0f * vsv * vsv);
        bP = DT_ / (rh * DH_);
        cl2mP = (DT_ / DH_) * (lam + 2.0f * mu);
        clamP = (DT_ / DH_) * lam;
        cmuP  = (DT_ / DH_) * mu;
        bQ = DT_ / (__ldg(&rho[gq]) * DH_);
    }

    // wavefields, zero initial conditions
    float vx[RZ_]  = {}, vz[RZ_]  = {};
    float txx[RZ_] = {}, tzz[RZ_] = {}, txz[RZ_] = {};
    #pragma unroll
    for (int r = 0; r < RZ_; ++r) {
        s_vx[r][x] = 0.f; s_vz[r][x] = 0.f; s_txx[r][x] = 0.f; s_txz[r][x] = 0.f;
    }

    // source ownership
    const int ssz = src_loc[2 * b];
    const int ssx = src_loc[2 * b + 1];
    const bool is_src = ((ssz / RZ_) == tz) && (x == ssx);
    const int src_lr  = ssz % RZ_;
    const bool src_at_a = has_top && (ssz == tz * RZ_ - 1)  && (x == ssx);
    const bool src_at_p = has_bot && (ssz == tz * RZ_ + RZ_) && (x == ssx);

    // receiver ownership: thread index doubles as receiver index
    bool is_rec = false;
    int my_lrz = 0, my_rx = 0;
    if (x < NREC_) {
        int rz = rec_loc[2 * x];
        my_rx  = rec_loc[2 * x + 1];
        if ((rz / RZ_) == tz) { is_rec = true; my_lrz = rz % RZ_; }
    }

    __syncthreads();

    for (int i = 1; i <= NIT_; ++i) {
        const int t1 = 2 * i - 1;
        const int t2 = 2 * i;
        const float w1 = __ldg(&xsrc[b * NT_ + (t1 - 1)]);
        const float w2 = __ldg(&xsrc[b * NT_ + (t2 - 1)]);

        // ---- V1 interior rows 1..RZ-2 (no message dependence) ----
        #pragma unroll
        for (int r = 1; r < RZ_ - 1; ++r) {
            float txx_c = txx[r], txz_c = txz[r];
            vx[r] += bc[r] * ((s_txx[r][xp] - txx_c) + (txz_c - txz[r - 1]));
            vz[r] += bc[r] * ((txz_c - s_txz[r][xm]) + (tzz[r + 1] - tzz[r]));
        }

        // ---- per-lane tagged message poll (ONE RTT, no barrier) ----
        const int want = i - 1;
        const int pr = want & 1;
        // top side values (from c-1's dn)
        float t_vx=0, t_txx_x=0, t_txz_x=0, t_txx_xp=0, t_txz_xm=0;
        float t_vz=0, t_tzz=0, t_txz2=0, t_txz2_xm=0, t_vz2=0, t_tzz2=0;
        // bottom side values (from c+1's up)
        float b_vx=0, b_txx_x=0, b_txz_x=0, b_txx_xp=0, b_txz_xm=0;
        float b_vz=0, b_tzz=0, b_vx2=0, b_txx2=0, b_txz2=0, b_tzz2=0, b_txx2_xp=0;
        {
            const Chunk* dn = has_top ? &g_dnC[pr][c - 1][0][0] : nullptr;
            const Chunk* up = has_bot ? &g_upC[pr][c + 1][0][0] : nullptr;
            bool top_ok = !has_top, bot_ok = !has_bot;
            do {
                if (!top_ok) {
                    int g0,g1,g2,g3,g4,g5; float u;
                    ldcg_v4(dn + 0*NX_ + x,  t_vx,   t_txx_x, t_txz_x,  g0);
                    ldcg_v4(dn + 0*NX_ + xm, u,      u,       t_txz_xm, g1);
                    ldcg_v4(dn + 0*NX_ + xp, u,      t_txx_xp,u,        g2);
                    ldcg_v4(dn + 1*NX_ + x,  t_vz,   t_tzz,   t_txz2,   g3);
                    ldcg_v4(dn + 1*NX_ + xm, u,      u,       t_txz2_xm,g4);
                    ldcg_v4(dn + 2*NX_ + x,  t_vz2,  t_tzz2,  u,        g5);
                    top_ok = (g0==want)&(g1==want)&(g2==want)&(g3==want)&(g4==want)&(g5==want);
                }
                if (!bot_ok) {
                    int g0,g1,g2,g3,g4,g5; float u;
                    ldcg_v4(up + 0*NX_ + x,  b_vx,   b_txx_x, b_txz_x,  g0);
                    ldcg_v4(up + 0*NX_ + xm, u,      u,       b_txz_xm, g1);
                    ldcg_v4(up + 0*NX_ + xp, u,      b_txx_xp,u,        g2);
                    ldcg_v4(up + 1*NX_ + x,  b_vz,   b_tzz,   b_vx2,    g3);
                    ldcg_v4(up + 2*NX_ + x,  b_txx2, b_txz2,  b_tzz2,   g4);
                    ldcg_v4(up + 2*NX_ + xp, b_txx2_xp, u,    u,        g5);
                    bot_ok = (g0==want)&(g1==want)&(g2==want)&(g3==want)&(g4==want)&(g5==want);
                }
            } while (!(top_ok && bot_ok));
        }
        // overlap: independent interior SMEM stores
        #pragma unroll
        for (int r = 1; r < RZ_ - 1; ++r) { s_vx[r][x] = vx[r]; s_vz[r][x] = vz[r]; }

        // ---- ghost t+1 velocities ----
        float vza1=0, vzb1=0, vxa1=0, vxp1=0, vxq1=0, vzp1=0;
        if (has_top) {
            vza1 = t_vz  + bA * ((t_txz_x  - t_txz_xm)  + (tzz[0] - t_tzz));
            vzb1 = t_vz2 + bB * ((t_txz2   - t_txz2_xm) + (t_tzz  - t_tzz2));
            vxa1 = t_vx  + bA * ((t_txx_xp - t_txx_x)   + (t_txz_x - t_txz2));
        }
        if (has_bot) {
            vxp1 = b_vx  + bP * ((b_txx_xp  - b_txx_x) + (b_txz_x - txz[RZ_ - 1]));
            vxq1 = b_vx2 + bQ * ((b_txx2_xp - b_txx2)  + (b_txz2  - b_txz_x));
            vzp1 = b_vz  + bP * ((b_txz_x   - b_txz_xm) + (b_tzz2 - b_tzz));
        }

        // ---- V1 edge rows 0 and RZ-1 ----
        {
            float txz_zm = has_top ? t_txz_x : txz[0];
            vx[0] += bc[0] * ((s_txx[0][xp] - txx[0]) + (txz[0] - txz_zm));
            vz[0] += bc[0] * ((txz[0] - s_txz[0][xm]) + (tzz[1] - tzz[0]));
            constexpr int r = RZ_ - 1;
            float tzz_zp = has_bot ? b_tzz : tzz[r];
            vx[r] += bc[r] * ((s_txx[r][xp] - txx[r]) + (txz[r] - txz[r - 1]));
            vz[r] += bc[r] * ((txz[r] - s_txz[r][xm]) + (tzz_zp - tzz[r]));
        }
        s_vx[0][x] = vx[0];             s_vz[0][x] = vz[0];
        s_vx[RZ_ - 1][x] = vx[RZ_ - 1]; s_vz[RZ_ - 1][x] = vz[RZ_ - 1];
        sh_vxa1[x] = vxa1; sh_vza1[x] = vza1;
        sh_vxp1[x] = vxp1; sh_vzp1[x] = vzp1;
        __syncthreads();   // (2)

        // record t1
        if (is_rec) {
            int base = (t1 - 1) * (NREC_ * 2 * B_) + x * (2 * B_);
            out[base + b]      = s_vx[my_lrz][my_rx];
            out[base + B_ + b] = s_vz[my_lrz][my_rx];
        }

        // ---- ghost t+1 edge stresses ----
        float tzza1=0, txza1=0, txxp1=0, tzzp1=0, txzp1=0;
        if (has_top) {
            tzza1 = t_tzz + clamA * (vxa1 - sh_vxa1[xm]) + cl2mA * (vza1 - vzb1);
            if (src_at_a) tzza1 += w1;
            txza1 = t_txz_x + cmuA * ((vx[0] - vxa1) + (sh_vza1[xp] - vza1));
        }
        if (has_bot) {
            float dvx_p = vxp1 - sh_vxp1[xm];
            float dvz_p = vzp1 - vz[RZ_ - 1];
            txxp1 = b_txx_x + cl2mP * dvx_p + clamP * dvz_p;
            tzzp1 = b_tzz   + clamP * dvx_p + cl2mP * dvz_p;
            if (src_at_p) { txxp1 += w1; tzzp1 += w1; }
            txzp1 = b_txz_x + cmuP * ((vxq1 - vxp1) + (sh_vzp1[xp] - vzp1));
        }

        // ------------------ S1 ------------------
        #pragma unroll
        for (int r = 0; r < RZ_; ++r) {
            float vx_c = vx[r], vz_c = vz[r];
            float vz_zm = (r > 0) ? vz[r - 1] : (has_top ? vza1 : vz_c);
            float vx_zp = (r < RZ_ - 1) ? vx[r + 1] : (has_bot ? vxp1 : vx_c);
            float dvx = vx_c - s_vx[r][xm];
            float dvz = vz_c - vz_zm;
            txx[r] += cl2m[r] * dvx + clam[r] * dvz;
            tzz[r] += clam[r] * dvx + cl2m[r] * dvz;
            txz[r] += cmu[r] * ((vx_zp - vx_c) + (s_vz[r][xp] - vz_c));
        }
        if (is_src) {
            #pragma unroll
            for (int r = 0; r < RZ_; ++r)
                if (r == src_lr) { txx[r] += w1; tzz[r] += w1; }
        }
        #pragma unroll
        for (int r = 0; r < RZ_; ++r) { s_txx[r][x] = txx[r]; s_txz[r][x] = txz[r]; }
        sh_txza1[x] = txza1; sh_txxp1[x] = txxp1;
        __syncthreads();   // (3)

        // ---- ghost t+2 edge velocities ----
        float vza2 = 0, vxp2 = 0;
        if (has_top)
            vza2 = vza1 + bA * ((txza1 - sh_txza1[xm]) + (tzz[0] - tzza1));
        if (has_bot)
            vxp2 = vxp1 + bP * ((sh_txxp1[xp] - txxp1) + (txzp1 - txz[RZ_ - 1]));

        // ------------------ V2 ------------------
        #pragma unroll
        for (int r = 0; r < RZ_; ++r) {
            float txx_c = txx[r], txz_c = txz[r];
            float txz_zm = (r > 0) ? txz[r - 1] : (has_top ? txza1 : txz_c);
            float tzz_zp = (r < RZ_ - 1) ? tzz[r + 1] : (has_bot ? tzzp1 : tzz[r]);
            vx[r] += bc[r] * ((s_txx[r][xp] - txx_c) + (txz_c - txz_zm));
            vz[r] += bc[r] * ((txz_c - s_txz[r][xm]) + (tzz_zp - tzz[r]));
        }
        #pragma unroll
        for (int r = 0; r < RZ_; ++r) { s_vx[r][x] = vx[r]; s_vz[r][x] = vz[r]; }
        __syncthreads();   // (4)

        // ---- S2 apron rows {0,1,RZ-2,RZ-1} first, then per-lane publish ----
        #pragma unroll
        for (int rr = 0; rr < 4; ++rr) {
            const int r = (rr < 2) ? rr : RZ_ - 4 + rr;   // 0,1,RZ-2,RZ-1
            float vx_c = vx[r], vz_c = vz[r];
            float vz_zm = (r > 0) ? vz[r - 1] : (has_top ? vza2 : vz_c);
            float vx_zp = (r < RZ_ - 1) ? vx[r + 1] : (has_bot ? vxp2 : vx_c);
            float dvx = vx_c - s_vx[r][xm];
            float dvz = vz_c - vz_zm;
            txx[r] += cl2m[r] * dvx + clam[r] * dvz;
            tzz[r] += clam[r] * dvx + cl2m[r] * dvz;
            txz[r] += cmu[r] * ((vx_zp - vx_c) + (s_vz[r][xp] - vz_c));
            if (is_src && r == src_lr) { txx[r] += w2; tzz[r] += w2; }
        }
        // publish t+2 apron, tag = i (per-lane, no barrier, no flag)
        {
            const int pw = i & 1;
            Chunk* dnp = &g_dnC[pw][c][0][0];
            stcg_v4(dnp + 0*NX_ + x, vx[RZ_-1], txx[RZ_-1], txz[RZ_-1], i);
            stcg_v4(dnp + 1*NX_ + x, vz[RZ_-1], tzz[RZ_-1], txz[RZ_-2], i);
            stcg_v4(dnp + 2*NX_ + x, vz[RZ_-2], tzz[RZ_-2], 0.f,        i);
            Chunk* upp = &g_upC[pw][c][0][0];
            stcg_v4(upp + 0*NX_ + x, vx[0], txx[0], txz[0], i);
            stcg_v4(upp + 1*NX_ + x, vz[0], tzz[0], vx[1],  i);
            stcg_v4(upp + 2*NX_ + x, txx[1], txz[1], tzz[1], i);
        }

        // record t2 (s_vx/s_vz valid since sync 4; S2 doesn't touch them)
        if (is_rec) {
            int base = (t2 - 1) * (NREC_ * 2 * B_) + x * (2 * B_);
            out[base + b]      = s_vx[my_lrz][my_rx];
            out[base + B_ + b] = s_vz[my_lrz][my_rx];
        }

        // ---- S2 interior rows 2..RZ-3 (off the inter-CTA critical path) ----
        #pragma unroll
        for (int r = 2; r < RZ_ - 2; ++r) {
            float vx_c = vx[r], vz_c = vz[r];
            float dvx = vx_c - s_vx[r][xm];
            float dvz = vz_c - vz[r - 1];
            txx[r] += cl2m[r] * dvx + clam[r] * dvz;
            tzz[r] += clam[r] * dvx + cl2m[r] * dvz;
            txz[r] += cmu[r] * ((vx[r + 1] - vx_c) + (s_vz[r][xp] - vz_c));
            if (is_src && r == src_lr) { txx[r] += w2; tzz[r] += w2; }
        }
        #pragma unroll
        for (int r = 0; r < RZ_; ++r) { s_txx[r][x] = txx[r]; s_txz[r][x] = txz[r]; }
        __syncthreads();   // (6) — next iter's V1 reads s_txx/s_txz
    }
}

extern "C" void kernel_launch(void* const* d_in, const int* in_sizes, int n_in,
                              void* d_out, int out_size) {
    const float* x   = (const float*)d_in[0];
    const float* vp  = (const float*)d_in[1];
    const float* vs  = (const float*)d_in[2];
    const float* rho = (const float*)d_in[3];
    const int* src   = (const int*)d_in[4];
    const int* rec   = (const int*)d_in[5];
    float* out = (float*)d_out;

    // re-zero message slots (tags -> 0) so every graph replay is identical
    int n = 2 * NCTA_ * 3 * NX_ * 4;
    init_msgs_kernel<<<(n + 255) / 256, 256>>>();
    wave_kernel<<<NCTA_, NX_>>>(x, vp, vs, rho, src, rec, out);
}